// round 9
// baseline (speedup 1.0000x reference)
#include <cuda_runtime.h>

// AttentionConv: q,k,v = 1x1 convs; per-channel softmax over 7x7 window of
// q*(k+bias); out = sum attn*v.  B=4, C=Cout=64, H=W=64, K=7, PAD=3.
//
// R9: batch-pipelined PDL overlap.  qkv is fma-bound (MUFU idle), attn is
//     MUFU-bound (fma slack) -> overlap them.  8 launches on one stream,
//     all with ProgrammaticStreamSerialization: qkv_b | attn_b per batch.
//     qkv triggers at start (reads only stable inputs); attn griddepsync's
//     before reading g_q/k/v and triggers after committing them to smem,
//     so qkv_{b+1} runs concurrent with attn_b's mainloop.  Cross-replay
//     WAR safe: qkv_0(N+1) chains after attn_3(N)'s post-consumption
//     trigger, transitively after every attn_b(N) consumed its inputs.
//     qkv blocks split 2x by oc (32oc x 64px) to stay dense per-batch.

#define LOG2E 1.4426950408889634f

__device__ float g_q[4 * 64 * 64 * 64];
__device__ float g_k[4 * 64 * 64 * 64];
__device__ float g_v[4 * 64 * 64 * 64];

__device__ __forceinline__ float ex2f(float v) {
    float r;
    asm("ex2.approx.ftz.f32 %0, %1;" : "=f"(r) : "f"(v));
    return r;
}

__device__ __forceinline__ unsigned long long fma_f32x2(
    unsigned long long a, unsigned long long b, unsigned long long c) {
    unsigned long long d;
    asm("fma.rn.f32x2 %0, %1, %2, %3;" : "=l"(d) : "l"(a), "l"(b), "l"(c));
    return d;
}

__device__ __forceinline__ unsigned long long dupf(float v) {
    unsigned long long r;
    asm("mov.b64 %0, {%1, %1};" : "=l"(r) : "f"(v));
    return r;
}

// ---------------------------------------------------------------------------
// Kernel 1: qkv projections for ONE batch.  grid (64 px-tiles, 3 mats,
// 2 oc-halves) = 384 blocks, 128 threads.  Block: 32 oc x 64 px.
// ws[c][o] = W^T slice (stride 34, coalesced LDG + 2-way STS scatter);
// xs[c][p].  Thread tile 4 oc x 4 px as 2 o-pairs -> 8 FFMA2 per c.
// ---------------------------------------------------------------------------
#define WSTR 34

__global__ __launch_bounds__(128) void qkv_kernel(
    const float* __restrict__ x, const float* __restrict__ y,
    const float* __restrict__ Wq, const float* __restrict__ Wk,
    const float* __restrict__ Wv, int b) {
    __shared__ __align__(16) float ws[32 * WSTR * 2];  // [c*34 + o], c<64 folded
    __shared__ __align__(16) float xs[64 * 64];

    cudaTriggerProgrammaticLaunchCompletion();

    const int mat = blockIdx.y;
    const float* Wsrc = (mat == 0) ? Wq : ((mat == 1) ? Wk : Wv);
    const float* src  = (mat == 2) ? y : x;
    float* dst = (mat == 0) ? g_q : ((mat == 1) ? g_k : g_v);

    const int tid = threadIdx.x;
    const int obase = blockIdx.z << 5;     // 0 or 32
    const int hw0 = blockIdx.x << 6;       // 64 px within this batch plane

    // coalesced W slice read (rows obase..obase+31), scatter-transpose
#pragma unroll
    for (int i = 0; i < 16; i++) {
        int idx = tid + i * 128;           // = o_local*64 + c
        ws[(idx & 63) * WSTR + (idx >> 6)] = Wsrc[(obase << 6) + idx];
    }
#pragma unroll
    for (int i = 0; i < 32; i++) {
        int idx = tid + i * 128;           // = c*64 + p
        xs[idx] = src[((b << 6) + (idx >> 6)) * 4096 + hw0 + (idx & 63)];
    }
    __syncthreads();

    const int o0 = (tid >> 4) << 2;        // 4 oc per thread (2 pairs), 0..28
    const int p0 = (tid & 15) << 2;        // 4 px

    unsigned long long acc[2][4];
#pragma unroll
    for (int i = 0; i < 2; i++)
#pragma unroll
        for (int j = 0; j < 4; j++) acc[i][j] = 0ULL;

#pragma unroll 8
    for (int cc = 0; cc < 64; cc++) {
        float4 xv = *(const float4*)(xs + (cc << 6) + p0);
        unsigned long long dx0 = dupf(xv.x);
        unsigned long long dx1 = dupf(xv.y);
        unsigned long long dx2 = dupf(xv.z);
        unsigned long long dx3 = dupf(xv.w);
        const float* wrow = ws + cc * WSTR + o0;
        unsigned long long wp0 = *(const unsigned long long*)(wrow);
        unsigned long long wp1 = *(const unsigned long long*)(wrow + 2);
        acc[0][0] = fma_f32x2(wp0, dx0, acc[0][0]);
        acc[0][1] = fma_f32x2(wp0, dx1, acc[0][1]);
        acc[0][2] = fma_f32x2(wp0, dx2, acc[0][2]);
        acc[0][3] = fma_f32x2(wp0, dx3, acc[0][3]);
        acc[1][0] = fma_f32x2(wp1, dx0, acc[1][0]);
        acc[1][1] = fma_f32x2(wp1, dx1, acc[1][1]);
        acc[1][2] = fma_f32x2(wp1, dx2, acc[1][2]);
        acc[1][3] = fma_f32x2(wp1, dx3, acc[1][3]);
    }

#pragma unroll
    for (int o2 = 0; o2 < 2; o2++) {
        float2 v0 = *reinterpret_cast<float2*>(&acc[o2][0]);
        float2 v1 = *reinterpret_cast<float2*>(&acc[o2][1]);
        float2 v2 = *reinterpret_cast<float2*>(&acc[o2][2]);
        float2 v3 = *reinterpret_cast<float2*>(&acc[o2][3]);
        float* base = dst + ((b << 6) + obase + o0 + 2 * o2) * 4096 + hw0 + p0;
        *(float4*)(base)        = make_float4(v0.x, v1.x, v2.x, v3.x);
        *(float4*)(base + 4096) = make_float4(v0.y, v1.y, v2.y, v3.y);
    }
}

// ---------------------------------------------------------------------------
// Kernel 2: windowed per-channel softmax-attention for ONE batch.
// grid (4 h-tiles, 64 channels), 128 threads.  PDL: griddepsync before any
// g_q/k/v access; trigger after committing them to smem (lets qkv_{b+1} go).
// ---------------------------------------------------------------------------
#define KSW 76

__global__ __launch_bounds__(128, 7) void attn_kernel(
    const float* __restrict__ rel_h, const float* __restrict__ rel_w,
    float* __restrict__ out, int b) {
    __shared__ __align__(16) float ks[22 * KSW];
    __shared__ __align__(16) float vs[22 * KSW];

    const int tid = threadIdx.x;
    const int h0 = blockIdx.x << 4;
    const int c  = blockIdx.y;
    const int plane = ((b << 6) + c) << 12;

    const int ty = tid >> 4;
    const int w0 = (tid & 15) << 2;
    const int r0 = h0 + (ty << 1);

    // bias from harness inputs (stable, no dependency)
    const float* bp = (c < 32) ? (rel_h + c * 7) : (rel_w + (c - 32) * 7);
    float bias7[7];
#pragma unroll
    for (int j = 0; j < 7; j++) bias7[j] = __ldg(bp + j);

    // zero-fill padded tiles while waiting on qkv_b
    float4 z4 = make_float4(0.f, 0.f, 0.f, 0.f);
    for (int i = tid; i < (22 * KSW) / 4; i += 128) {
        ((float4*)ks)[i] = z4;
        ((float4*)vs)[i] = z4;
    }
    __syncthreads();

    cudaGridDependencySynchronize();       // qkv_b results now visible

    const float* kp = g_k + plane;
    const float* vp = g_v + plane;
#pragma unroll
    for (int it = 0; it < 3; it++) {
        int i = tid + it * 128;            // 0..351 (22 rows x 16 col-groups)
        int r = i >> 4, c4 = (i & 15) << 2;
        int gr = h0 - 3 + r;
        if ((i < 352) && ((unsigned)gr < 64u)) {
            float4 kv = *(const float4*)(kp + (gr << 6) + c4);
            float4 vv = *(const float4*)(vp + (gr << 6) + c4);
            int s0 = r * KSW + 3 + c4;
            ks[s0] = kv.x; ks[s0 + 1] = kv.y; ks[s0 + 2] = kv.z; ks[s0 + 3] = kv.w;
            vs[s0] = vv.x; vs[s0 + 1] = vv.y; vs[s0 + 2] = vv.z; vs[s0 + 3] = vv.w;
        }
    }
    const float4 qa = *(const float4*)(g_q + plane + (r0 << 6) + w0);
    const float4 qb = *(const float4*)(g_q + plane + ((r0 + 1) << 6) + w0);

    // all g_* inputs consumed -> let qkv_{b+1} launch
    cudaTriggerProgrammaticLaunchCompletion();
    __syncthreads();

    float q2[8] = {qa.x * LOG2E, qa.y * LOG2E, qa.z * LOG2E, qa.w * LOG2E,
                   qb.x * LOG2E, qb.y * LOG2E, qb.z * LOG2E, qb.w * LOG2E};
    float s[8], a[8];
#pragma unroll
    for (int i = 0; i < 8; i++) { s[i] = 0.f; a[i] = 0.f; }

    if (c < 32) {
#pragma unroll
        for (int j = 0; j < 8; j++) {
            const float* krow = &ks[((ty << 1) + j) * KSW + w0];
            const float* vrow = &vs[((ty << 1) + j) * KSW + w0];
            float kr[12], vr[12];
            *(float4*)(kr)     = *(const float4*)(krow);
            *(float4*)(kr + 4) = *(const float4*)(krow + 4);
            *(float4*)(kr + 8) = *(const float4*)(krow + 8);
            *(float4*)(vr)     = *(const float4*)(vrow);
            *(float4*)(vr + 4) = *(const float4*)(vrow + 4);
            *(float4*)(vr + 8) = *(const float4*)(vrow + 8);
            if (j < 7) {
                float qb0[4];
#pragma unroll
                for (int i = 0; i < 4; i++) qb0[i] = q2[i] * bias7[j];
#pragma unroll
                for (int kw = 0; kw < 7; kw++)
#pragma unroll
                    for (int i = 0; i < 4; i++) {
                        float e = ex2f(fmaf(q2[i], kr[i + kw], qb0[i]));
                        s[i] += e;
                        a[i] = fmaf(e, vr[i + kw], a[i]);
                    }
            }
            if (j >= 1) {
                float qb1[4];
#pragma unroll
                for (int i = 0; i < 4; i++) qb1[i] = q2[4 + i] * bias7[j - 1];
#pragma unroll
                for (int kw = 0; kw < 7; kw++)
#pragma unroll
                    for (int i = 0; i < 4; i++) {
                        float e = ex2f(fmaf(q2[4 + i], kr[i + kw], qb1[i]));
                        s[4 + i] += e;
                        a[4 + i] = fmaf(e, vr[i + kw], a[4 + i]);
                    }
            }
        }
    } else {
#pragma unroll
        for (int j = 0; j < 8; j++) {
            const float* krow = &ks[((ty << 1) + j) * KSW + w0];
            const float* vrow = &vs[((ty << 1) + j) * KSW + w0];
            float kr[12], vr[12];
            *(float4*)(kr)     = *(const float4*)(krow);
            *(float4*)(kr + 4) = *(const float4*)(krow + 4);
            *(float4*)(kr + 8) = *(const float4*)(krow + 8);
            *(float4*)(vr)     = *(const float4*)(vrow);
            *(float4*)(vr + 4) = *(const float4*)(vrow + 4);
            *(float4*)(vr + 8) = *(const float4*)(vrow + 8);
            if (j < 7) {
#pragma unroll
                for (int kw = 0; kw < 7; kw++) {
                    float bb = bias7[kw];
#pragma unroll
                    for (int i = 0; i < 4; i++) {
                        float e = ex2f(q2[i] * (kr[i + kw] + bb));
                        s[i] += e;
                        a[i] = fmaf(e, vr[i + kw], a[i]);
                    }
                }
            }
            if (j >= 1) {
#pragma unroll
                for (int kw = 0; kw < 7; kw++) {
                    float bb = bias7[kw];
#pragma unroll
                    for (int i = 0; i < 4; i++) {
                        float e = ex2f(q2[4 + i] * (kr[i + kw] + bb));
                        s[4 + i] += e;
                        a[4 + i] = fmaf(e, vr[i + kw], a[4 + i]);
                    }
                }
            }
        }
    }

    float4 o0, o1;
    o0.x = __fdividef(a[0], s[0]);
    o0.y = __fdividef(a[1], s[1]);
    o0.z = __fdividef(a[2], s[2]);
    o0.w = __fdividef(a[3], s[3]);
    o1.x = __fdividef(a[4], s[4]);
    o1.y = __fdividef(a[5], s[5]);
    o1.z = __fdividef(a[6], s[6]);
    o1.w = __fdividef(a[7], s[7]);
    *(float4*)(out + plane + (r0 << 6) + w0) = o0;
    *(float4*)(out + plane + ((r0 + 1) << 6) + w0) = o1;
}

extern "C" void kernel_launch(void* const* d_in, const int* in_sizes, int n_in,
                              void* d_out, int out_size) {
    const float* x     = (const float*)d_in[0];
    const float* y     = (const float*)d_in[1];
    const float* Wq    = (const float*)d_in[2];
    const float* Wk    = (const float*)d_in[3];
    const float* Wv    = (const float*)d_in[4];
    const float* rel_h = (const float*)d_in[5];
    const float* rel_w = (const float*)d_in[6];
    float* out = (float*)d_out;

    cudaLaunchAttribute attr;
    attr.id = cudaLaunchAttributeProgrammaticStreamSerialization;
    attr.val.programmaticStreamSerializationAllowed = 1;

    for (int b = 0; b < 4; b++) {
        cudaLaunchConfig_t cq = {};
        cq.gridDim = dim3(64, 3, 2);
        cq.blockDim = dim3(128, 1, 1);
        cq.stream = 0;
        cq.attrs = &attr;
        cq.numAttrs = 1;
        cudaLaunchKernelEx(&cq, qkv_kernel, x, y, Wq, Wk, Wv, b);

        cudaLaunchConfig_t ca = {};
        ca.gridDim = dim3(4, 64, 1);
        ca.blockDim = dim3(128, 1, 1);
        ca.stream = 0;
        ca.attrs = &attr;
        ca.numAttrs = 1;
        cudaLaunchKernelEx(&ca, attn_kernel, rel_h, rel_w, out, b);
    }
}

// round 10
// speedup vs baseline: 1.3665x; 1.3665x over previous
#include <cuda_runtime.h>

// AttentionConv: q,k,v = 1x1 convs; per-channel softmax over 7x7 window of
// q*(k+bias); out = sum attn*v.  B=4, C=Cout=64, H=W=64, K=7, PAD=3.
//
// R10: R8 full-grid kernels (qkv 768 blocks fma-bound; attn 1024 blocks
//      MUFU-bound) + PDL cross-kernel overlap WITHOUT shrinking grids
//      (R9 showed per-batch splitting kills occupancy).  qkv computes in
//      registers and griddepsyncs only before its epilogue STG, so its
//      fma mainloop overlaps the previous attn's MUFU mainloop across
//      graph replays.  attn griddepsyncs before reading g_q/k/v and
//      triggers after consuming them.  Dispatch order prevents deadlock;
//      WAR safe (qkv stores gated on prior attn completion).

#define LOG2E 1.4426950408889634f

__device__ float g_q[4 * 64 * 64 * 64];
__device__ float g_k[4 * 64 * 64 * 64];
__device__ float g_v[4 * 64 * 64 * 64];

__device__ __forceinline__ float ex2f(float v) {
    float r;
    asm("ex2.approx.ftz.f32 %0, %1;" : "=f"(r) : "f"(v));
    return r;
}

__device__ __forceinline__ unsigned long long fma_f32x2(
    unsigned long long a, unsigned long long b, unsigned long long c) {
    unsigned long long d;
    asm("fma.rn.f32x2 %0, %1, %2, %3;" : "=l"(d) : "l"(a), "l"(b), "l"(c));
    return d;
}

__device__ __forceinline__ unsigned long long dupf(float v) {
    unsigned long long r;
    asm("mov.b64 %0, {%1, %1};" : "=l"(r) : "f"(v));
    return r;
}

// ---------------------------------------------------------------------------
// Kernel 1: qkv projections (R3/R8 GEMM).  128 threads, 64o x 64px tile,
// 768 blocks.  Trigger at start; griddepsync ONLY before the g_ stores.
// ---------------------------------------------------------------------------
#define WSTR 66

__global__ __launch_bounds__(128) void qkv_kernel(
    const float* __restrict__ x, const float* __restrict__ y,
    const float* __restrict__ Wq, const float* __restrict__ Wk,
    const float* __restrict__ Wv) {
    __shared__ __align__(16) float ws[64 * WSTR];
    __shared__ __align__(16) float xs[64 * 64];

    cudaTriggerProgrammaticLaunchCompletion();

    const int mat = blockIdx.y;
    const float* Wsrc = (mat == 0) ? Wq : ((mat == 1) ? Wk : Wv);
    const float* src  = (mat == 2) ? y : x;
    float* dst = (mat == 0) ? g_q : ((mat == 1) ? g_k : g_v);

    const int tid = threadIdx.x;
    const int pix0 = blockIdx.x * 64;
    const int b = pix0 >> 12;
    const int hw0 = pix0 & 4095;

#pragma unroll
    for (int i = 0; i < 32; i++) {
        int idx = tid + i * 128;           // = o*64 + c
        ws[(idx & 63) * WSTR + (idx >> 6)] = Wsrc[idx];
    }
#pragma unroll
    for (int i = 0; i < 32; i++) {
        int idx = tid + i * 128;           // = c*64 + p
        xs[idx] = src[((b << 6) + (idx >> 6)) * 4096 + hw0 + (idx & 63)];
    }
    __syncthreads();

    const int o0 = (tid >> 4) << 3;
    const int p0 = (tid & 15) << 2;

    unsigned long long acc[4][4];
#pragma unroll
    for (int i = 0; i < 4; i++)
#pragma unroll
        for (int j = 0; j < 4; j++) acc[i][j] = 0ULL;

#pragma unroll 4
    for (int cc = 0; cc < 64; cc++) {
        float4 xv = *(const float4*)(xs + (cc << 6) + p0);
        unsigned long long dx0 = dupf(xv.x);
        unsigned long long dx1 = dupf(xv.y);
        unsigned long long dx2 = dupf(xv.z);
        unsigned long long dx3 = dupf(xv.w);
        const float* wrow = ws + cc * WSTR + o0;
        unsigned long long wp0 = *(const unsigned long long*)(wrow);
        unsigned long long wp1 = *(const unsigned long long*)(wrow + 2);
        unsigned long long wp2 = *(const unsigned long long*)(wrow + 4);
        unsigned long long wp3 = *(const unsigned long long*)(wrow + 6);
        acc[0][0] = fma_f32x2(wp0, dx0, acc[0][0]);
        acc[0][1] = fma_f32x2(wp0, dx1, acc[0][1]);
        acc[0][2] = fma_f32x2(wp0, dx2, acc[0][2]);
        acc[0][3] = fma_f32x2(wp0, dx3, acc[0][3]);
        acc[1][0] = fma_f32x2(wp1, dx0, acc[1][0]);
        acc[1][1] = fma_f32x2(wp1, dx1, acc[1][1]);
        acc[1][2] = fma_f32x2(wp1, dx2, acc[1][2]);
        acc[1][3] = fma_f32x2(wp1, dx3, acc[1][3]);
        acc[2][0] = fma_f32x2(wp2, dx0, acc[2][0]);
        acc[2][1] = fma_f32x2(wp2, dx1, acc[2][1]);
        acc[2][2] = fma_f32x2(wp2, dx2, acc[2][2]);
        acc[2][3] = fma_f32x2(wp2, dx3, acc[2][3]);
        acc[3][0] = fma_f32x2(wp3, dx0, acc[3][0]);
        acc[3][1] = fma_f32x2(wp3, dx1, acc[3][1]);
        acc[3][2] = fma_f32x2(wp3, dx2, acc[3][2]);
        acc[3][3] = fma_f32x2(wp3, dx3, acc[3][3]);
    }

    // wait for the previous attn grid (stream predecessor) before
    // overwriting g_q/k/v it reads
    cudaGridDependencySynchronize();

#pragma unroll
    for (int o2 = 0; o2 < 4; o2++) {
        float2 v0 = *reinterpret_cast<float2*>(&acc[o2][0]);
        float2 v1 = *reinterpret_cast<float2*>(&acc[o2][1]);
        float2 v2 = *reinterpret_cast<float2*>(&acc[o2][2]);
        float2 v3 = *reinterpret_cast<float2*>(&acc[o2][3]);
        float* base = dst + ((b << 6) + o0 + 2 * o2) * 4096 + hw0 + p0;
        *(float4*)(base)        = make_float4(v0.x, v1.x, v2.x, v3.x);
        *(float4*)(base + 4096) = make_float4(v0.y, v1.y, v2.y, v3.y);
    }
}

// ---------------------------------------------------------------------------
// Kernel 2: windowed per-channel softmax-attention (R8 full grid).
// zero-fill -> griddepsync -> load g_ -> commit smem -> trigger -> mainloop.
// ---------------------------------------------------------------------------
#define KSW 76

__global__ __launch_bounds__(128, 7) void attn_kernel(
    const float* __restrict__ rel_h, const float* __restrict__ rel_w,
    float* __restrict__ out) {
    __shared__ __align__(16) float ks[22 * KSW];
    __shared__ __align__(16) float vs[22 * KSW];

    const int tid = threadIdx.x;
    const int h0 = blockIdx.x << 4;
    const int c  = blockIdx.y;
    const int b  = blockIdx.z;
    const int plane = ((b << 6) + c) << 12;

    const int ty = tid >> 4;
    const int w0 = (tid & 15) << 2;
    const int r0 = h0 + (ty << 1);

    // bias from harness inputs (stable, no dependency)
    const float* bp = (c < 32) ? (rel_h + c * 7) : (rel_w + (c - 32) * 7);
    float bias7[7];
#pragma unroll
    for (int j = 0; j < 7; j++) bias7[j] = __ldg(bp + j);

    // zero-fill padded tiles while qkv finishes
    float4 z4 = make_float4(0.f, 0.f, 0.f, 0.f);
    for (int i = tid; i < (22 * KSW) / 4; i += 128) {
        ((float4*)ks)[i] = z4;
        ((float4*)vs)[i] = z4;
    }
    __syncthreads();

    cudaGridDependencySynchronize();       // qkv results now visible

    const float* kp = g_k + plane;
    const float* vp = g_v + plane;
#pragma unroll
    for (int it = 0; it < 3; it++) {
        int i = tid + it * 128;            // 0..351 (22 rows x 16 col-groups)
        int r = i >> 4, c4 = (i & 15) << 2;
        int gr = h0 - 3 + r;
        if ((i < 352) && ((unsigned)gr < 64u)) {
            float4 kv = *(const float4*)(kp + (gr << 6) + c4);
            float4 vv = *(const float4*)(vp + (gr << 6) + c4);
            int s0 = r * KSW + 3 + c4;
            ks[s0] = kv.x; ks[s0 + 1] = kv.y; ks[s0 + 2] = kv.z; ks[s0 + 3] = kv.w;
            vs[s0] = vv.x; vs[s0 + 1] = vv.y; vs[s0 + 2] = vv.z; vs[s0 + 3] = vv.w;
        }
    }
    const float4 qa = *(const float4*)(g_q + plane + (r0 << 6) + w0);
    const float4 qb = *(const float4*)(g_q + plane + ((r0 + 1) << 6) + w0);

    // inputs consumed -> allow next qkv to launch (its stores still wait
    // on this grid's completion)
    cudaTriggerProgrammaticLaunchCompletion();
    __syncthreads();

    float q2[8] = {qa.x * LOG2E, qa.y * LOG2E, qa.z * LOG2E, qa.w * LOG2E,
                   qb.x * LOG2E, qb.y * LOG2E, qb.z * LOG2E, qb.w * LOG2E};
    float s[8], a[8];
#pragma unroll
    for (int i = 0; i < 8; i++) { s[i] = 0.f; a[i] = 0.f; }

    if (c < 32) {
#pragma unroll
        for (int j = 0; j < 8; j++) {
            const float* krow = &ks[((ty << 1) + j) * KSW + w0];
            const float* vrow = &vs[((ty << 1) + j) * KSW + w0];
            float kr[12], vr[12];
            *(float4*)(kr)     = *(const float4*)(krow);
            *(float4*)(kr + 4) = *(const float4*)(krow + 4);
            *(float4*)(kr + 8) = *(const float4*)(krow + 8);
            *(float4*)(vr)     = *(const float4*)(vrow);
            *(float4*)(vr + 4) = *(const float4*)(vrow + 4);
            *(float4*)(vr + 8) = *(const float4*)(vrow + 8);
            if (j < 7) {
                float qb0[4];
#pragma unroll
                for (int i = 0; i < 4; i++) qb0[i] = q2[i] * bias7[j];
#pragma unroll
                for (int kw = 0; kw < 7; kw++)
#pragma unroll
                    for (int i = 0; i < 4; i++) {
                        float e = ex2f(fmaf(q2[i], kr[i + kw], qb0[i]));
                        s[i] += e;
                        a[i] = fmaf(e, vr[i + kw], a[i]);
                    }
            }
            if (j >= 1) {
                float qb1[4];
#pragma unroll
                for (int i = 0; i < 4; i++) qb1[i] = q2[4 + i] * bias7[j - 1];
#pragma unroll
                for (int kw = 0; kw < 7; kw++)
#pragma unroll
                    for (int i = 0; i < 4; i++) {
                        float e = ex2f(fmaf(q2[4 + i], kr[i + kw], qb1[i]));
                        s[4 + i] += e;
                        a[4 + i] = fmaf(e, vr[i + kw], a[4 + i]);
                    }
            }
        }
    } else {
#pragma unroll
        for (int j = 0; j < 8; j++) {
            const float* krow = &ks[((ty << 1) + j) * KSW + w0];
            const float* vrow = &vs[((ty << 1) + j) * KSW + w0];
            float kr[12], vr[12];
            *(float4*)(kr)     = *(const float4*)(krow);
            *(float4*)(kr + 4) = *(const float4*)(krow + 4);
            *(float4*)(kr + 8) = *(const float4*)(krow + 8);
            *(float4*)(vr)     = *(const float4*)(vrow);
            *(float4*)(vr + 4) = *(const float4*)(vrow + 4);
            *(float4*)(vr + 8) = *(const float4*)(vrow + 8);
            if (j < 7) {
#pragma unroll
                for (int kw = 0; kw < 7; kw++) {
                    float bb = bias7[kw];
#pragma unroll
                    for (int i = 0; i < 4; i++) {
                        float e = ex2f(q2[i] * (kr[i + kw] + bb));
                        s[i] += e;
                        a[i] = fmaf(e, vr[i + kw], a[i]);
                    }
                }
            }
            if (j >= 1) {
#pragma unroll
                for (int kw = 0; kw < 7; kw++) {
                    float bb = bias7[kw];
#pragma unroll
                    for (int i = 0; i < 4; i++) {
                        float e = ex2f(q2[4 + i] * (kr[i + kw] + bb));
                        s[4 + i] += e;
                        a[4 + i] = fmaf(e, vr[i + kw], a[4 + i]);
                    }
                }
            }
        }
    }

    float4 o0, o1;
    o0.x = __fdividef(a[0], s[0]);
    o0.y = __fdividef(a[1], s[1]);
    o0.z = __fdividef(a[2], s[2]);
    o0.w = __fdividef(a[3], s[3]);
    o1.x = __fdividef(a[4], s[4]);
    o1.y = __fdividef(a[5], s[5]);
    o1.z = __fdividef(a[6], s[6]);
    o1.w = __fdividef(a[7], s[7]);
    *(float4*)(out + plane + (r0 << 6) + w0) = o0;
    *(float4*)(out + plane + ((r0 + 1) << 6) + w0) = o1;
}

extern "C" void kernel_launch(void* const* d_in, const int* in_sizes, int n_in,
                              void* d_out, int out_size) {
    const float* x     = (const float*)d_in[0];
    const float* y     = (const float*)d_in[1];
    const float* Wq    = (const float*)d_in[2];
    const float* Wk    = (const float*)d_in[3];
    const float* Wv    = (const float*)d_in[4];
    const float* rel_h = (const float*)d_in[5];
    const float* rel_w = (const float*)d_in[6];
    float* out = (float*)d_out;

    cudaLaunchAttribute attr;
    attr.id = cudaLaunchAttributeProgrammaticStreamSerialization;
    attr.val.programmaticStreamSerializationAllowed = 1;

    cudaLaunchConfig_t cq = {};
    cq.gridDim = dim3(256, 3, 1);
    cq.blockDim = dim3(128, 1, 1);
    cq.stream = 0;
    cq.attrs = &attr;
    cq.numAttrs = 1;
    cudaLaunchKernelEx(&cq, qkv_kernel, x, y, Wq, Wk, Wv);

    cudaLaunchConfig_t ca = {};
    ca.gridDim = dim3(4, 64, 4);
    ca.blockDim = dim3(128, 1, 1);
    ca.stream = 0;
    ca.attrs = &attr;
    ca.numAttrs = 1;
    cudaLaunchKernelEx(&ca, attn_kernel, rel_h, rel_w, out);
}